// round 6
// baseline (speedup 1.0000x reference)
#include <cuda_runtime.h>
#include <cuda_bf16.h>

// Problem shape (fixed by the dataset):
//   x : [16, 512, 64, 64] f32
//   s : [16, 512, 1, 4096] f32
//   z : [16, 1, 512, 1]   f32
//   wq: [1,1,5], wk: [1,1,5], wv: [512,1,3,3]
// Output: out [16,512,64,64], s_new [16,512,1,4096], z_new [16,1,512,1]

#define B 16
#define C 512
#define HW 4096
#define BC (B * C)            // 8192
#define OUT_ELEMS (BC * HW)   // 33554432

__device__ float g_y[BC];
__device__ unsigned g_cnt[B];

__device__ __forceinline__ unsigned ld_acquire_gpu(const unsigned* p) {
    unsigned v;
    asm volatile("ld.acquire.gpu.u32 %0, [%1];" : "=r"(v) : "l"(p) : "memory");
    return v;
}

// ---------------------------------------------------------------------------
// Reset kernel: zero per-batch arrival counters (needed for every graph replay)
// ---------------------------------------------------------------------------
__global__ void reset_kernel() {
    if (threadIdx.x < B) g_cnt[threadIdx.x] = 0u;
}

// ---------------------------------------------------------------------------
// Fused single-pass kernel. One block per (b,c) plane; x read EXACTLY ONCE.
// Phase 1: load plane -> smem tile + block-reduce mean -> g_y, arrive on batch
//          counter. Thread 0 spins (acquire) until all 512 means of its batch
//          arrived, then computes Qf/Kf/coef/z_new.
// Phase 2: depthwise 3x3 conv + s_new = s + Kf*V ; out = coef * s_new.
// __launch_bounds__(256,4): 4 blocks/SM * 148 SMs = 592 >= 512 co-resident
// blocks per batch (deadlock-free; batches are contiguous in blockIdx).
// ---------------------------------------------------------------------------
#define TP 68   // tile pitch: 66 rows x 68 floats; (r*68 + col0) % 4 == 0

__global__ void __launch_bounds__(256, 4)
main_kernel(const float* __restrict__ x,
            const float* __restrict__ s,
            const float* __restrict__ z,
            const float* __restrict__ wq,
            const float* __restrict__ wk,
            const float* __restrict__ wv,
            float* __restrict__ out,
            float* __restrict__ s_new,
            float* __restrict__ z_new) {
    int bc = blockIdx.x;                  // contiguous per batch
    int b = bc >> 9;
    int c = bc & 511;
    size_t base = (size_t)bc * HW;
    int t = threadIdx.x;

    __shared__ float tile[66 * TP];
    __shared__ float ws[8];
    __shared__ float sKf, sCf;

    // Front-batched vector loads: 4x x + 4x s = 8 LDG.128 in flight per thread.
    const float4* xp = reinterpret_cast<const float4*>(x + base);
    const float4* sp = reinterpret_cast<const float4*>(s + base);
    float4 xa[4], sv[4];
#pragma unroll
    for (int k = 0; k < 4; k++) xa[k] = __ldcs(xp + t + k * 256);
#pragma unroll
    for (int k = 0; k < 4; k++) sv[k] = __ldcs(sp + t + k * 256);

    // Zero the halo ring while loads are in flight.
    if (t < 66) { tile[t] = 0.0f; tile[65 * TP + t] = 0.0f; }
    if (t < 64) { tile[(t + 1) * TP] = 0.0f; tile[(t + 1) * TP + 65] = 0.0f; }

    // Per-channel conv weights.
    float w[9];
#pragma unroll
    for (int j = 0; j < 9; j++) w[j] = __ldg(wv + c * 9 + j);

    // Scatter x into the haloed tile AND accumulate the plane sum from regs.
    float sum = 0.0f;
#pragma unroll
    for (int k = 0; k < 4; k++) {
        int q = t + k * 256;          // float4 index 0..1023
        int p = q << 2;               // pixel
        int r = p >> 6;               // row 0..63
        int col = p & 63;             // col (multiple of 4)
        float* dst = &tile[(r + 1) * TP + col + 1];
        dst[0] = xa[k].x; dst[1] = xa[k].y; dst[2] = xa[k].z; dst[3] = xa[k].w;
        sum += (xa[k].x + xa[k].y) + (xa[k].z + xa[k].w);
    }

    // Block reduction of the plane sum.
#pragma unroll
    for (int o = 16; o > 0; o >>= 1) sum += __shfl_xor_sync(0xffffffffu, sum, o);
    if ((t & 31) == 0) ws[t >> 5] = sum;
    __syncthreads();   // covers tile scatter + ws

    if (t == 0) {
        float s2 = ws[0];
#pragma unroll
        for (int j = 1; j < 8; j++) s2 += ws[j];
        g_y[bc] = s2 * (1.0f / (float)HW);
        __threadfence();                       // publish g_y before arrival
        atomicAdd(&g_cnt[b], 1u);

        // Wait until all 512 means of this batch are published.
        while (ld_acquire_gpu(&g_cnt[b]) < (unsigned)C) __nanosleep(40);

        // Channel conv (k=5, SAME) -> elu+1 -> Kf, coef, z_new.
        float q = 0.0f, k = 0.0f;
#pragma unroll
        for (int j = 0; j < 5; j++) {
            int cc = c + j - 2;
            float v = ((unsigned)cc < (unsigned)C) ? g_y[(b << 9) + cc] : 0.0f;
            q += __ldg(wq + j) * v;
            k += __ldg(wk + j) * v;
        }
        float Qf = (q > 0.0f) ? (q + 1.0f) : expf(q);
        float Kf = (k > 0.0f) ? (k + 1.0f) : expf(k);
        float zn = z[bc] + Kf;
        float qz = 1.0f / (Qf * (zn + 1e-6f));
        sKf = Kf;
        sCf = Qf * qz;
        z_new[bc] = zn;
    }
    __syncthreads();

    float Kf = sKf;
    float Cf = sCf;

    float4* op = reinterpret_cast<float4*>(out + base);
    float4* np = reinterpret_cast<float4*>(s_new + base);

#pragma unroll
    for (int k = 0; k < 4; k++) {
        int q = t + k * 256;
        int p = q << 2;
        int r = p >> 6;
        int col0 = p & 63;

        float a0 = 0.0f, a1 = 0.0f, a2 = 0.0f, a3 = 0.0f;
#pragma unroll
        for (int di = 0; di < 3; di++) {
            const float* rowp = &tile[(r + di) * TP + col0];
            float4 f4 = *reinterpret_cast<const float4*>(rowp);
            float2 f2 = *reinterpret_cast<const float2*>(rowp + 4);
            float w0 = w[di * 3 + 0], w1 = w[di * 3 + 1], w2 = w[di * 3 + 2];
            a0 = fmaf(w0, f4.x, fmaf(w1, f4.y, fmaf(w2, f4.z, a0)));
            a1 = fmaf(w0, f4.y, fmaf(w1, f4.z, fmaf(w2, f4.w, a1)));
            a2 = fmaf(w0, f4.z, fmaf(w1, f4.w, fmaf(w2, f2.x, a2)));
            a3 = fmaf(w0, f4.w, fmaf(w1, f2.x, fmaf(w2, f2.y, a3)));
        }

        float4 sn, ov;
        sn.x = sv[k].x + Kf * a0;
        sn.y = sv[k].y + Kf * a1;
        sn.z = sv[k].z + Kf * a2;
        sn.w = sv[k].w + Kf * a3;
        ov.x = Cf * sn.x;
        ov.y = Cf * sn.y;
        ov.z = Cf * sn.z;
        ov.w = Cf * sn.w;
        __stcs(np + q, sn);
        __stcs(op + q, ov);
    }
}

// ---------------------------------------------------------------------------
extern "C" void kernel_launch(void* const* d_in, const int* in_sizes, int n_in,
                              void* d_out, int out_size) {
    const float* x  = (const float*)d_in[0];
    const float* s  = (const float*)d_in[1];
    const float* z  = (const float*)d_in[2];
    const float* wq = (const float*)d_in[3];
    const float* wk = (const float*)d_in[4];
    const float* wv = (const float*)d_in[5];

    float* out   = (float*)d_out;                 // [BC, HW]
    float* s_new = out + (size_t)OUT_ELEMS;       // [BC, HW]
    float* z_new = s_new + (size_t)OUT_ELEMS;     // [BC]

    reset_kernel<<<1, 32>>>();
    main_kernel<<<BC, 256>>>(x, s, z, wq, wk, wv, out, s_new, z_new);
}

// round 7
// speedup vs baseline: 1.1854x; 1.1854x over previous
#include <cuda_runtime.h>
#include <cuda_bf16.h>

// Problem shape (fixed by the dataset):
//   x : [16, 512, 64, 64] f32
//   s : [16, 512, 1, 4096] f32
//   z : [16, 1, 512, 1]   f32
//   wq: [1,1,5], wk: [1,1,5], wv: [512,1,3,3]
// Output: out [16,512,64,64], s_new [16,512,1,4096], z_new [16,1,512,1]

#define B 16
#define C 512
#define HW 4096
#define BC (B * C)            // 8192
#define OUT_ELEMS (BC * HW)   // 33554432

#define GROUP_BATCHES 4
#define GROUP_PLANES (GROUP_BATCHES * C)   // 2048
#define NUM_GROUPS (B / GROUP_BATCHES)     // 4

__device__ float g_y[BC];

// ---------------------------------------------------------------------------
// Kernel 1: spatial mean for one group of batches. Default cache policy so the
// group's x slice (33.6 MB) stays resident in L2 for the main kernel.
// ---------------------------------------------------------------------------
__global__ void __launch_bounds__(256) mean_kernel(const float* __restrict__ x,
                                                   int bc_base) {
    int bc = bc_base + blockIdx.x;
    const float4* xp = reinterpret_cast<const float4*>(x + (size_t)bc * HW);
    int t = threadIdx.x;
    float sum = 0.0f;
#pragma unroll
    for (int k = 0; k < 4; k++) {
        float4 v = xp[t + k * 256];
        sum += (v.x + v.y) + (v.z + v.w);
    }
#pragma unroll
    for (int o = 16; o > 0; o >>= 1) sum += __shfl_xor_sync(0xffffffffu, sum, o);
    __shared__ float ws[8];
    if ((t & 31) == 0) ws[t >> 5] = sum;
    __syncthreads();
    if (t < 8) {
        float s2 = ws[t];
#pragma unroll
        for (int o = 4; o > 0; o >>= 1) s2 += __shfl_xor_sync(0xffu, s2, o);
        if (t == 0) g_y[bc] = s2 * (1.0f / (float)HW);
    }
}

// ---------------------------------------------------------------------------
// Kernel 2 (per group): Qf/Kf/coef/z_new (thread 0) + depthwise 3x3 conv +
//   s_new = s + Kf*V ; out = coef * s_new
// x loads hit L2 (slice was just streamed by mean_kernel). s/out/s_new use
// streaming hints so they don't evict the x slice.
// ---------------------------------------------------------------------------
#define TP 68   // tile pitch: 66 rows x 68 floats; (r*68 + col0) % 4 == 0

__global__ void __launch_bounds__(256) main_kernel(const float* __restrict__ x,
                                                   const float* __restrict__ s,
                                                   const float* __restrict__ z,
                                                   const float* __restrict__ wq,
                                                   const float* __restrict__ wk,
                                                   const float* __restrict__ wv,
                                                   float* __restrict__ out,
                                                   float* __restrict__ s_new,
                                                   float* __restrict__ z_new,
                                                   int bc_base) {
    int bc = bc_base + blockIdx.x;
    int b = bc >> 9;
    int c = bc & 511;
    size_t base = (size_t)bc * HW;
    int t = threadIdx.x;

    __shared__ float tile[66 * TP];
    __shared__ float sKf, sCf;

    // Front-batched vector loads: 4x x (L2 hits) + 4x s (streaming).
    const float4* xp = reinterpret_cast<const float4*>(x + base);
    const float4* sp = reinterpret_cast<const float4*>(s + base);
    float4 xa[4], sv[4];
#pragma unroll
    for (int k = 0; k < 4; k++) xa[k] = __ldg(xp + t + k * 256);
#pragma unroll
    for (int k = 0; k < 4; k++) sv[k] = __ldcs(sp + t + k * 256);

    // Zero the halo ring while loads are in flight.
    if (t < 66) { tile[t] = 0.0f; tile[65 * TP + t] = 0.0f; }
    if (t < 64) { tile[(t + 1) * TP] = 0.0f; tile[(t + 1) * TP + 65] = 0.0f; }

    // Per-channel weights.
    float w[9];
#pragma unroll
    for (int j = 0; j < 9; j++) w[j] = __ldg(wv + c * 9 + j);

    // Thread 0: channel conv (k=5, SAME) -> elu+1 -> Kf, coef, z_new.
    if (t == 0) {
        float q = 0.0f, k = 0.0f;
#pragma unroll
        for (int j = 0; j < 5; j++) {
            int cc = c + j - 2;
            float v = ((unsigned)cc < (unsigned)C) ? g_y[(b << 9) + cc] : 0.0f;
            q += __ldg(wq + j) * v;
            k += __ldg(wk + j) * v;
        }
        float Qf = (q > 0.0f) ? (q + 1.0f) : expf(q);
        float Kf = (k > 0.0f) ? (k + 1.0f) : expf(k);
        float zn = z[bc] + Kf;
        float qz = 1.0f / (Qf * (zn + 1e-6f));
        sKf = Kf;
        sCf = Qf * qz;
        z_new[bc] = zn;
    }

    // Scatter x into the haloed tile (no predication, no division).
#pragma unroll
    for (int k = 0; k < 4; k++) {
        int q = t + k * 256;          // float4 index 0..1023
        int p = q << 2;               // pixel
        int r = p >> 6;               // row 0..63
        int col = p & 63;             // col (multiple of 4)
        float* dst = &tile[(r + 1) * TP + col + 1];
        dst[0] = xa[k].x; dst[1] = xa[k].y; dst[2] = xa[k].z; dst[3] = xa[k].w;
    }
    __syncthreads();

    float Kf = sKf;
    float Cf = sCf;

    float4* op = reinterpret_cast<float4*>(out + base);
    float4* np = reinterpret_cast<float4*>(s_new + base);

#pragma unroll
    for (int k = 0; k < 4; k++) {
        int q = t + k * 256;
        int p = q << 2;
        int r = p >> 6;
        int col0 = p & 63;

        float a0 = 0.0f, a1 = 0.0f, a2 = 0.0f, a3 = 0.0f;
#pragma unroll
        for (int di = 0; di < 3; di++) {
            const float* rowp = &tile[(r + di) * TP + col0];
            float4 f4 = *reinterpret_cast<const float4*>(rowp);
            float2 f2 = *reinterpret_cast<const float2*>(rowp + 4);
            float w0 = w[di * 3 + 0], w1 = w[di * 3 + 1], w2 = w[di * 3 + 2];
            a0 = fmaf(w0, f4.x, fmaf(w1, f4.y, fmaf(w2, f4.z, a0)));
            a1 = fmaf(w0, f4.y, fmaf(w1, f4.z, fmaf(w2, f4.w, a1)));
            a2 = fmaf(w0, f4.z, fmaf(w1, f4.w, fmaf(w2, f2.x, a2)));
            a3 = fmaf(w0, f4.w, fmaf(w1, f2.x, fmaf(w2, f2.y, a3)));
        }

        float4 sn, ov;
        sn.x = sv[k].x + Kf * a0;
        sn.y = sv[k].y + Kf * a1;
        sn.z = sv[k].z + Kf * a2;
        sn.w = sv[k].w + Kf * a3;
        ov.x = Cf * sn.x;
        ov.y = Cf * sn.y;
        ov.z = Cf * sn.z;
        ov.w = Cf * sn.w;
        __stcs(np + q, sn);
        __stcs(op + q, ov);
    }
}

// ---------------------------------------------------------------------------
extern "C" void kernel_launch(void* const* d_in, const int* in_sizes, int n_in,
                              void* d_out, int out_size) {
    const float* x  = (const float*)d_in[0];
    const float* s  = (const float*)d_in[1];
    const float* z  = (const float*)d_in[2];
    const float* wq = (const float*)d_in[3];
    const float* wk = (const float*)d_in[4];
    const float* wv = (const float*)d_in[5];

    float* out   = (float*)d_out;                 // [BC, HW]
    float* s_new = out + (size_t)OUT_ELEMS;       // [BC, HW]
    float* z_new = s_new + (size_t)OUT_ELEMS;     // [BC]

    for (int g = 0; g < NUM_GROUPS; g++) {
        int bc_base = g * GROUP_PLANES;
        mean_kernel<<<GROUP_PLANES, 256>>>(x, bc_base);
        main_kernel<<<GROUP_PLANES, 256>>>(x, s, z, wq, wk, wv,
                                           out, s_new, z_new, bc_base);
    }
}

// round 8
// speedup vs baseline: 1.2019x; 1.0139x over previous
#include <cuda_runtime.h>
#include <cuda_bf16.h>

// Problem shape (fixed by the dataset):
//   x : [16, 512, 64, 64] f32
//   s : [16, 512, 1, 4096] f32
//   z : [16, 1, 512, 1]   f32
//   wq: [1,1,5], wk: [1,1,5], wv: [512,1,3,3]
// Output: out [16,512,64,64], s_new [16,512,1,4096], z_new [16,1,512,1]

#define B 16
#define C 512
#define HW 4096
#define BC (B * C)            // 8192
#define OUT_ELEMS (BC * HW)   // 33554432

#define GROUP_BATCHES 4
#define GROUP_PLANES (GROUP_BATCHES * C)   // 2048
#define NUM_GROUPS (B / GROUP_BATCHES)     // 4

__device__ float g_y[BC];

#define TP 68   // tile pitch: 66 rows x 68 floats; (r*68 + col0) % 4 == 0

// ---------------------------------------------------------------------------
// Fused pipelined kernel. Blocks [0, mean_count) compute the spatial mean for
// planes mean_base+i (x read with DEFAULT policy -> allocates in L2 for the
// NEXT launch's main blocks). Blocks [mean_count, mean_count+main_count) run
// the conv+epilogue for planes main_base+i (x from L2 via the PREVIOUS
// launch's mean; all s/out/s_new traffic uses streaming hints to protect the
// L2-resident x slice). Launch-order gives the g_y dependency for free.
// ---------------------------------------------------------------------------
__global__ void __launch_bounds__(256) fused_kernel(const float* __restrict__ x,
                                                    const float* __restrict__ s,
                                                    const float* __restrict__ z,
                                                    const float* __restrict__ wq,
                                                    const float* __restrict__ wk,
                                                    const float* __restrict__ wv,
                                                    float* __restrict__ out,
                                                    float* __restrict__ s_new,
                                                    float* __restrict__ z_new,
                                                    int mean_base, int mean_count,
                                                    int main_base) {
    int t = threadIdx.x;

    if ((int)blockIdx.x < mean_count) {
        // ---------------- mean role ----------------
        int bc = mean_base + blockIdx.x;
        const float4* xp = reinterpret_cast<const float4*>(x + (size_t)bc * HW);
        float sum = 0.0f;
#pragma unroll
        for (int k = 0; k < 4; k++) {
            float4 v = xp[t + k * 256];          // default policy: allocate in L2
            sum += (v.x + v.y) + (v.z + v.w);
        }
#pragma unroll
        for (int o = 16; o > 0; o >>= 1) sum += __shfl_xor_sync(0xffffffffu, sum, o);
        __shared__ float ws[8];
        if ((t & 31) == 0) ws[t >> 5] = sum;
        __syncthreads();
        if (t < 8) {
            float s2 = ws[t];
#pragma unroll
            for (int o = 4; o > 0; o >>= 1) s2 += __shfl_xor_sync(0xffu, s2, o);
            if (t == 0) g_y[bc] = s2 * (1.0f / (float)HW);
        }
        return;
    }

    // ---------------- main role ----------------
    int bc = main_base + ((int)blockIdx.x - mean_count);
    int b = bc >> 9;
    int c = bc & 511;
    size_t base = (size_t)bc * HW;

    __shared__ float tile[66 * TP];
    __shared__ float sKf, sCf;

    // Front-batched vector loads: 4x x (L2 hits; last use -> evict) + 4x s.
    const float4* xp = reinterpret_cast<const float4*>(x + base);
    const float4* sp = reinterpret_cast<const float4*>(s + base);
    float4 xa[4], sv[4];
#pragma unroll
    for (int k = 0; k < 4; k++) xa[k] = __ldcs(xp + t + k * 256);
#pragma unroll
    for (int k = 0; k < 4; k++) sv[k] = __ldcs(sp + t + k * 256);

    // Zero the halo ring while loads are in flight.
    if (t < 66) { tile[t] = 0.0f; tile[65 * TP + t] = 0.0f; }
    if (t < 64) { tile[(t + 1) * TP] = 0.0f; tile[(t + 1) * TP + 65] = 0.0f; }

    // Per-channel weights.
    float w[9];
#pragma unroll
    for (int j = 0; j < 9; j++) w[j] = __ldg(wv + c * 9 + j);

    // Thread 0: channel conv (k=5, SAME) -> elu+1 -> Kf, coef, z_new.
    if (t == 0) {
        float q = 0.0f, k = 0.0f;
#pragma unroll
        for (int j = 0; j < 5; j++) {
            int cc = c + j - 2;
            float v = ((unsigned)cc < (unsigned)C) ? g_y[(b << 9) + cc] : 0.0f;
            q += __ldg(wq + j) * v;
            k += __ldg(wk + j) * v;
        }
        float Qf = (q > 0.0f) ? (q + 1.0f) : expf(q);
        float Kf = (k > 0.0f) ? (k + 1.0f) : expf(k);
        float zn = z[bc] + Kf;
        float qz = 1.0f / (Qf * (zn + 1e-6f));
        sKf = Kf;
        sCf = Qf * qz;
        z_new[bc] = zn;
    }

    // Scatter x into the haloed tile.
#pragma unroll
    for (int k = 0; k < 4; k++) {
        int q = t + k * 256;          // float4 index 0..1023
        int p = q << 2;               // pixel
        int r = p >> 6;               // row 0..63
        int col = p & 63;             // col (multiple of 4)
        float* dst = &tile[(r + 1) * TP + col + 1];
        dst[0] = xa[k].x; dst[1] = xa[k].y; dst[2] = xa[k].z; dst[3] = xa[k].w;
    }
    __syncthreads();

    float Kf = sKf;
    float Cf = sCf;

    float4* op = reinterpret_cast<float4*>(out + base);
    float4* np = reinterpret_cast<float4*>(s_new + base);

#pragma unroll
    for (int k = 0; k < 4; k++) {
        int q = t + k * 256;
        int p = q << 2;
        int r = p >> 6;
        int col0 = p & 63;

        float a0 = 0.0f, a1 = 0.0f, a2 = 0.0f, a3 = 0.0f;
#pragma unroll
        for (int di = 0; di < 3; di++) {
            const float* rowp = &tile[(r + di) * TP + col0];
            float4 f4 = *reinterpret_cast<const float4*>(rowp);
            float2 f2 = *reinterpret_cast<const float2*>(rowp + 4);
            float w0 = w[di * 3 + 0], w1 = w[di * 3 + 1], w2 = w[di * 3 + 2];
            a0 = fmaf(w0, f4.x, fmaf(w1, f4.y, fmaf(w2, f4.z, a0)));
            a1 = fmaf(w0, f4.y, fmaf(w1, f4.z, fmaf(w2, f4.w, a1)));
            a2 = fmaf(w0, f4.z, fmaf(w1, f4.w, fmaf(w2, f2.x, a2)));
            a3 = fmaf(w0, f4.w, fmaf(w1, f2.x, fmaf(w2, f2.y, a3)));
        }

        float4 sn, ov;
        sn.x = sv[k].x + Kf * a0;
        sn.y = sv[k].y + Kf * a1;
        sn.z = sv[k].z + Kf * a2;
        sn.w = sv[k].w + Kf * a3;
        ov.x = Cf * sn.x;
        ov.y = Cf * sn.y;
        ov.z = Cf * sn.z;
        ov.w = Cf * sn.w;
        __stcs(np + q, sn);
        __stcs(op + q, ov);
    }
}

// ---------------------------------------------------------------------------
extern "C" void kernel_launch(void* const* d_in, const int* in_sizes, int n_in,
                              void* d_out, int out_size) {
    const float* x  = (const float*)d_in[0];
    const float* s  = (const float*)d_in[1];
    const float* z  = (const float*)d_in[2];
    const float* wq = (const float*)d_in[3];
    const float* wk = (const float*)d_in[4];
    const float* wv = (const float*)d_in[5];

    float* out   = (float*)d_out;                 // [BC, HW]
    float* s_new = out + (size_t)OUT_ELEMS;       // [BC, HW]
    float* z_new = s_new + (size_t)OUT_ELEMS;     // [BC]

    // Software pipeline over NUM_GROUPS+1 launches:
    //   launch g carries mean(group g) [if g < NUM_GROUPS]
    //   and main(group g-1)            [if g >= 1]
    for (int g = 0; g <= NUM_GROUPS; g++) {
        int mean_count = (g < NUM_GROUPS) ? GROUP_PLANES : 0;
        int main_count = (g >= 1) ? GROUP_PLANES : 0;
        int mean_base = g * GROUP_PLANES;
        int main_base = (g - 1) * GROUP_PLANES;
        fused_kernel<<<mean_count + main_count, 256>>>(
            x, s, z, wq, wk, wv, out, s_new, z_new,
            mean_base, mean_count, main_base);
    }
}

// round 9
// speedup vs baseline: 1.2473x; 1.0378x over previous
#include <cuda_runtime.h>
#include <cuda_bf16.h>

// Problem shape (fixed by the dataset):
//   x : [16, 512, 64, 64] f32
//   s : [16, 512, 1, 4096] f32
//   z : [16, 1, 512, 1]   f32
//   wq: [1,1,5], wk: [1,1,5], wv: [512,1,3,3]
// Output: out [16,512,64,64], s_new [16,512,1,4096], z_new [16,1,512,1]

#define B 16
#define C 512
#define HW 4096
#define BC (B * C)            // 8192
#define OUT_ELEMS (BC * HW)   // 33554432

#define GROUP_BATCHES 4
#define GROUP_PLANES (GROUP_BATCHES * C)   // 2048
#define NUM_GROUPS (B / GROUP_BATCHES)     // 4

__device__ float g_y[BC];

#define TP 68   // tile pitch: 66 rows x 68 floats; (r*68 + col0) % 4 == 0

// ---------------------------------------------------------------------------
// Pipelined fused kernel, roles INTERLEAVED at block granularity:
//   both roles present: even bid -> mean(group g), odd bid -> main(group g-1)
// so every wave carries both the DRAM-heavy mean stream (loads next group's x
// into L2, default policy) and the L2-consuming main blocks. Launch order
// provides the g_y dependency. s/out/s_new use streaming hints everywhere.
// __launch_bounds__(256,5): cap regs ~51 -> 5 blocks/SM, better latency hiding.
// ---------------------------------------------------------------------------
__global__ void __launch_bounds__(256, 5)
fused_kernel(const float* __restrict__ x,
             const float* __restrict__ s,
             const float* __restrict__ z,
             const float* __restrict__ wq,
             const float* __restrict__ wk,
             const float* __restrict__ wv,
             float* __restrict__ out,
             float* __restrict__ s_new,
             float* __restrict__ z_new,
             int mean_base, int mean_count,
             int main_base, int main_count) {
    int t = threadIdx.x;
    int bid = (int)blockIdx.x;

    bool is_mean;
    int idx;
    if (mean_count == 0)      { is_mean = false; idx = bid; }
    else if (main_count == 0) { is_mean = true;  idx = bid; }
    else                      { is_mean = (bid & 1) == 0; idx = bid >> 1; }

    if (is_mean) {
        // ---------------- mean role: stream group g's x into L2 ----------------
        int bc = mean_base + idx;
        const float4* xp = reinterpret_cast<const float4*>(x + (size_t)bc * HW);
        float sum = 0.0f;
#pragma unroll
        for (int k = 0; k < 4; k++) {
            float4 v = xp[t + k * 256];          // default policy: allocate in L2
            sum += (v.x + v.y) + (v.z + v.w);
        }
#pragma unroll
        for (int o = 16; o > 0; o >>= 1) sum += __shfl_xor_sync(0xffffffffu, sum, o);
        __shared__ float ws[8];
        if ((t & 31) == 0) ws[t >> 5] = sum;
        __syncthreads();
        if (t < 8) {
            float s2 = ws[t];
#pragma unroll
            for (int o = 4; o > 0; o >>= 1) s2 += __shfl_xor_sync(0xffu, s2, o);
            if (t == 0) g_y[bc] = s2 * (1.0f / (float)HW);
        }
        return;
    }

    // ---------------- main role: conv + epilogue for group g-1 ----------------
    int bc = main_base + idx;
    int b = bc >> 9;
    int c = bc & 511;
    size_t base = (size_t)bc * HW;

    __shared__ float tile[66 * TP];
    __shared__ float sKf, sCf;

    // x loads: L2 hits from the previous launch's mean role; last use -> evict.
    const float4* xp = reinterpret_cast<const float4*>(x + base);
    float4 xa[4];
#pragma unroll
    for (int k = 0; k < 4; k++) xa[k] = __ldcs(xp + t + k * 256);

    // Zero the halo ring while loads are in flight.
    if (t < 66) { tile[t] = 0.0f; tile[65 * TP + t] = 0.0f; }
    if (t < 64) { tile[(t + 1) * TP] = 0.0f; tile[(t + 1) * TP + 65] = 0.0f; }

    // Per-channel weights.
    float w[9];
#pragma unroll
    for (int j = 0; j < 9; j++) w[j] = __ldg(wv + c * 9 + j);

    // Thread 0: channel conv (k=5, SAME) -> elu+1 -> Kf, coef, z_new.
    if (t == 0) {
        float q = 0.0f, k = 0.0f;
#pragma unroll
        for (int j = 0; j < 5; j++) {
            int cc = c + j - 2;
            float v = ((unsigned)cc < (unsigned)C) ? g_y[(b << 9) + cc] : 0.0f;
            q += __ldg(wq + j) * v;
            k += __ldg(wk + j) * v;
        }
        float Qf = (q > 0.0f) ? (q + 1.0f) : expf(q);
        float Kf = (k > 0.0f) ? (k + 1.0f) : expf(k);
        float zn = z[bc] + Kf;
        float qz = 1.0f / (Qf * (zn + 1e-6f));
        sKf = Kf;
        sCf = Qf * qz;
        z_new[bc] = zn;
    }

    // Scatter x into the haloed tile.
#pragma unroll
    for (int k = 0; k < 4; k++) {
        int q = t + k * 256;          // float4 index 0..1023
        int p = q << 2;               // pixel
        int r = p >> 6;               // row 0..63
        int col = p & 63;             // col (multiple of 4)
        float* dst = &tile[(r + 1) * TP + col + 1];
        dst[0] = xa[k].x; dst[1] = xa[k].y; dst[2] = xa[k].z; dst[3] = xa[k].w;
    }
    __syncthreads();

    float Kf = sKf;
    float Cf = sCf;

    const float4* sp = reinterpret_cast<const float4*>(s + base);
    float4* op = reinterpret_cast<float4*>(out + base);
    float4* np = reinterpret_cast<float4*>(s_new + base);

#pragma unroll
    for (int k = 0; k < 4; k++) {
        int q = t + k * 256;
        int p = q << 2;
        int r = p >> 6;
        int col0 = p & 63;

        float4 sv = __ldcs(sp + q);   // streaming; loaded per-iteration (low regs)

        float a0 = 0.0f, a1 = 0.0f, a2 = 0.0f, a3 = 0.0f;
#pragma unroll
        for (int di = 0; di < 3; di++) {
            const float* rowp = &tile[(r + di) * TP + col0];
            float4 f4 = *reinterpret_cast<const float4*>(rowp);
            float2 f2 = *reinterpret_cast<const float2*>(rowp + 4);
            float w0 = w[di * 3 + 0], w1 = w[di * 3 + 1], w2 = w[di * 3 + 2];
            a0 = fmaf(w0, f4.x, fmaf(w1, f4.y, fmaf(w2, f4.z, a0)));
            a1 = fmaf(w0, f4.y, fmaf(w1, f4.z, fmaf(w2, f4.w, a1)));
            a2 = fmaf(w0, f4.z, fmaf(w1, f4.w, fmaf(w2, f2.x, a2)));
            a3 = fmaf(w0, f4.w, fmaf(w1, f2.x, fmaf(w2, f2.y, a3)));
        }

        float4 sn, ov;
        sn.x = sv.x + Kf * a0;
        sn.y = sv.y + Kf * a1;
        sn.z = sv.z + Kf * a2;
        sn.w = sv.w + Kf * a3;
        ov.x = Cf * sn.x;
        ov.y = Cf * sn.y;
        ov.z = Cf * sn.z;
        ov.w = Cf * sn.w;
        __stcs(np + q, sn);
        __stcs(op + q, ov);
    }
}

// ---------------------------------------------------------------------------
extern "C" void kernel_launch(void* const* d_in, const int* in_sizes, int n_in,
                              void* d_out, int out_size) {
    const float* x  = (const float*)d_in[0];
    const float* s  = (const float*)d_in[1];
    const float* z  = (const float*)d_in[2];
    const float* wq = (const float*)d_in[3];
    const float* wk = (const float*)d_in[4];
    const float* wv = (const float*)d_in[5];

    float* out   = (float*)d_out;                 // [BC, HW]
    float* s_new = out + (size_t)OUT_ELEMS;       // [BC, HW]
    float* z_new = s_new + (size_t)OUT_ELEMS;     // [BC]

    // Software pipeline over NUM_GROUPS+1 launches:
    //   launch g: mean(group g) [g < NUM_GROUPS]  interleaved with
    //             main(group g-1) [g >= 1]
    for (int g = 0; g <= NUM_GROUPS; g++) {
        int mean_count = (g < NUM_GROUPS) ? GROUP_PLANES : 0;
        int main_count = (g >= 1) ? GROUP_PLANES : 0;
        int mean_base = g * GROUP_PLANES;
        int main_base = (g - 1) * GROUP_PLANES;
        fused_kernel<<<mean_count + main_count, 256>>>(
            x, s, z, wq, wk, wv, out, s_new, z_new,
            mean_base, mean_count, main_base, main_count);
    }
}

// round 11
// speedup vs baseline: 1.3014x; 1.0434x over previous
#include <cuda_runtime.h>
#include <cuda_bf16.h>

// Problem shape (fixed by the dataset):
//   x : [16, 512, 64, 64] f32
//   s : [16, 512, 1, 4096] f32
//   z : [16, 1, 512, 1]   f32
//   wq: [1,1,5], wk: [1,1,5], wv: [512,1,3,3]
// Output: out [16,512,64,64], s_new [16,512,1,4096], z_new [16,1,512,1]

#define B 16
#define C 512
#define HW 4096
#define BC (B * C)            // 8192
#define OUT_ELEMS (BC * HW)   // 33554432

__device__ float g_y[BC];

// Protected-class L2 load (evict_last). sm_103 ptxas requires 256-bit width
// for this modifier -> use v4.b64 (32 bytes = 8 floats).
struct f8 { float v[8]; };
__device__ __forceinline__ f8 ld_evict_last_f8(const void* p) {
    unsigned long long a, b, c, d;
    asm volatile("ld.global.L2::evict_last.v4.b64 {%0,%1,%2,%3}, [%4];"
                 : "=l"(a), "=l"(b), "=l"(c), "=l"(d) : "l"(p));
    f8 r;
    r.v[0] = __uint_as_float((unsigned)(a & 0xffffffffu));
    r.v[1] = __uint_as_float((unsigned)(a >> 32));
    r.v[2] = __uint_as_float((unsigned)(b & 0xffffffffu));
    r.v[3] = __uint_as_float((unsigned)(b >> 32));
    r.v[4] = __uint_as_float((unsigned)(c & 0xffffffffu));
    r.v[5] = __uint_as_float((unsigned)(c >> 32));
    r.v[6] = __uint_as_float((unsigned)(d & 0xffffffffu));
    r.v[7] = __uint_as_float((unsigned)(d >> 32));
    return r;
}

// ---------------------------------------------------------------------------
// Kernel 1: spatial mean of x per (b,c). x loaded with L2::evict_last so the
// tail of x (~120 MB) stays pinned in L2's protected class for main_kernel.
// Each thread: 2 x 32-byte loads (plane = 4096 floats = 256 thr * 16 floats).
// ---------------------------------------------------------------------------
__global__ void __launch_bounds__(256) mean_kernel(const float* __restrict__ x) {
    int bc = blockIdx.x;
    const float* xp = x + (size_t)bc * HW;
    int t = threadIdx.x;
    float sum = 0.0f;
#pragma unroll
    for (int k = 0; k < 2; k++) {
        f8 v = ld_evict_last_f8(xp + (t + k * 256) * 8);
#pragma unroll
        for (int j = 0; j < 8; j++) sum += v.v[j];
    }
#pragma unroll
    for (int o = 16; o > 0; o >>= 1) sum += __shfl_xor_sync(0xffffffffu, sum, o);
    __shared__ float ws[8];
    if ((t & 31) == 0) ws[t >> 5] = sum;
    __syncthreads();
    if (t < 8) {
        float s2 = ws[t];
#pragma unroll
        for (int o = 4; o > 0; o >>= 1) s2 += __shfl_xor_sync(0xffu, s2, o);
        if (t == 0) g_y[bc] = s2 * (1.0f / (float)HW);
    }
}

// ---------------------------------------------------------------------------
// Kernel 2 (fused): Qf/Kf/coef/z_new (thread 0) + depthwise 3x3 conv +
//   s_new = s + Kf*V ; out = coef * s_new
// Reversed block order (consume L2 MRU planes first). x read with __ldcs
// (last use -> demote), s/out/s_new all streaming so only evict-first
// traffic competes with the protected x lines.
// __launch_bounds__(256,5): ~48 regs, higher occupancy to hide L2-hit latency.
// ---------------------------------------------------------------------------
#define TP 68   // tile pitch: 66 rows x 68 floats; (r*68 + col0) % 4 == 0

__global__ void __launch_bounds__(256, 5)
main_kernel(const float* __restrict__ x,
            const float* __restrict__ s,
            const float* __restrict__ z,
            const float* __restrict__ wq,
            const float* __restrict__ wk,
            const float* __restrict__ wv,
            float* __restrict__ out,
            float* __restrict__ s_new,
            float* __restrict__ z_new) {
    int bc = (BC - 1) - (int)blockIdx.x;   // reversed: MRU planes first
    int b = bc >> 9;
    int c = bc & 511;
    size_t base = (size_t)bc * HW;
    int t = threadIdx.x;

    __shared__ float tile[66 * TP];
    __shared__ float sKf, sCf;

    // x loads: should hit protected L2 lines; last use -> evict-first hint.
    const float4* xp = reinterpret_cast<const float4*>(x + base);
    float4 xa[4];
#pragma unroll
    for (int k = 0; k < 4; k++) xa[k] = __ldcs(xp + t + k * 256);

    // Zero the halo ring while loads are in flight.
    if (t < 66) { tile[t] = 0.0f; tile[65 * TP + t] = 0.0f; }
    if (t < 64) { tile[(t + 1) * TP] = 0.0f; tile[(t + 1) * TP + 65] = 0.0f; }

    // Per-channel weights.
    float w[9];
#pragma unroll
    for (int j = 0; j < 9; j++) w[j] = __ldg(wv + c * 9 + j);

    // Thread 0: channel conv (k=5, SAME) -> elu+1 -> Kf, coef, z_new.
    if (t == 0) {
        float q = 0.0f, k = 0.0f;
#pragma unroll
        for (int j = 0; j < 5; j++) {
            int cc = c + j - 2;
            float v = ((unsigned)cc < (unsigned)C) ? g_y[(b << 9) + cc] : 0.0f;
            q += __ldg(wq + j) * v;
            k += __ldg(wk + j) * v;
        }
        float Qf = (q > 0.0f) ? (q + 1.0f) : expf(q);
        float Kf = (k > 0.0f) ? (k + 1.0f) : expf(k);
        float zn = z[bc] + Kf;
        float qz = 1.0f / (Qf * (zn + 1e-6f));
        sKf = Kf;
        sCf = Qf * qz;
        z_new[bc] = zn;
    }

    // Scatter x into the haloed tile.
#pragma unroll
    for (int k = 0; k < 4; k++) {
        int q = t + k * 256;          // float4 index 0..1023
        int p = q << 2;               // pixel
        int r = p >> 6;               // row 0..63
        int col = p & 63;             // col (multiple of 4)
        float* dst = &tile[(r + 1) * TP + col + 1];
        dst[0] = xa[k].x; dst[1] = xa[k].y; dst[2] = xa[k].z; dst[3] = xa[k].w;
    }
    __syncthreads();

    float Kf = sKf;
    float Cf = sCf;

    const float4* sp = reinterpret_cast<const float4*>(s + base);
    float4* op = reinterpret_cast<float4*>(out + base);
    float4* np = reinterpret_cast<float4*>(s_new + base);

#pragma unroll
    for (int k = 0; k < 4; k++) {
        int q = t + k * 256;
        int p = q << 2;
        int r = p >> 6;
        int col0 = p & 63;

        float4 sv = __ldcs(sp + q);   // streaming; per-iteration (keeps regs low)

        float a0 = 0.0f, a1 = 0.0f, a2 = 0.0f, a3 = 0.0f;
#pragma unroll
        for (int di = 0; di < 3; di++) {
            const float* rowp = &tile[(r + di) * TP + col0];
            float4 f4 = *reinterpret_cast<const float4*>(rowp);
            float2 f2 = *reinterpret_cast<const float2*>(rowp + 4);
            float w0 = w[di * 3 + 0], w1 = w[di * 3 + 1], w2 = w[di * 3 + 2];
            a0 = fmaf(w0, f4.x, fmaf(w1, f4.y, fmaf(w2, f4.z, a0)));
            a1 = fmaf(w0, f4.y, fmaf(w1, f4.z, fmaf(w2, f4.w, a1)));
            a2 = fmaf(w0, f4.z, fmaf(w1, f4.w, fmaf(w2, f2.x, a2)));
            a3 = fmaf(w0, f4.w, fmaf(w1, f2.x, fmaf(w2, f2.y, a3)));
        }

        float4 sn, ov;
        sn.x = sv.x + Kf * a0;
        sn.y = sv.y + Kf * a1;
        sn.z = sv.z + Kf * a2;
        sn.w = sv.w + Kf * a3;
        ov.x = Cf * sn.x;
        ov.y = Cf * sn.y;
        ov.z = Cf * sn.z;
        ov.w = Cf * sn.w;
        __stcs(np + q, sn);
        __stcs(op + q, ov);
    }
}

// ---------------------------------------------------------------------------
extern "C" void kernel_launch(void* const* d_in, const int* in_sizes, int n_in,
                              void* d_out, int out_size) {
    const float* x  = (const float*)d_in[0];
    const float* s  = (const float*)d_in[1];
    const float* z  = (const float*)d_in[2];
    const float* wq = (const float*)d_in[3];
    const float* wk = (const float*)d_in[4];
    const float* wv = (const float*)d_in[5];

    float* out   = (float*)d_out;                 // [BC, HW]
    float* s_new = out + (size_t)OUT_ELEMS;       // [BC, HW]
    float* z_new = s_new + (size_t)OUT_ELEMS;     // [BC]

    mean_kernel<<<BC, 256>>>(x);
    main_kernel<<<BC, 256>>>(x, s, z, wq, wk, wv, out, s_new, z_new);
}